// round 2
// baseline (speedup 1.0000x reference)
#include <cuda_runtime.h>
#include <math.h>
#include <float.h>

#define NN   50000
#define EE   800000
#define HIDD 256

// ---------------- scratch (no allocations allowed) ----------------
__device__ float g_q   [(size_t)NN * HIDD];
__device__ float g_k   [(size_t)NN * HIDD];
__device__ float g_v   [(size_t)NN * HIDD];
__device__ float g_skip[(size_t)NN * HIDD];
__device__ int   g_counts[NN];
__device__ int   g_off[NN + 1];
__device__ int   g_cur[NN];
__device__ int   g_perm[EE];

// ---------------- SGEMM: C[M,256] = X[M,256] @ W[256,256] + b ----------------
// 128x64 block tile, BK=16, 256 threads, 8x4 micro-tile per thread.
__global__ __launch_bounds__(256) void sgemm_bias(
    const float* __restrict__ X, const float* __restrict__ W,
    const float* __restrict__ bias, int which, int M)
{
    __shared__ float As[16][128];   // transposed: As[k][m]
    __shared__ float Bs[16][64];

    float* C = (which == 0) ? g_q : (which == 1) ? g_k : (which == 2) ? g_v : g_skip;

    int tid = threadIdx.x;
    int tx  = tid & 15;     // n-dim, 16 * 4 = 64
    int ty  = tid >> 4;     // m-dim, 16 * 8 = 128
    int m0  = blockIdx.x * 128;
    int n0  = blockIdx.y * 64;

    float acc[8][4];
#pragma unroll
    for (int i = 0; i < 8; i++)
#pragma unroll
        for (int j = 0; j < 4; j++) acc[i][j] = 0.f;

    for (int k0 = 0; k0 < 256; k0 += 16) {
        // load A tile (128 x 16), transposed into As
#pragma unroll
        for (int r = 0; r < 2; r++) {
            int f4   = tid + 256 * r;
            int aRow = f4 >> 2;            // 0..127
            int aCol = (f4 & 3) << 2;      // 0,4,8,12
            int row  = m0 + aRow;
            float4 av = make_float4(0.f, 0.f, 0.f, 0.f);
            if (row < M)
                av = *(const float4*)(X + (size_t)row * 256 + k0 + aCol);
            As[aCol + 0][aRow] = av.x;
            As[aCol + 1][aRow] = av.y;
            As[aCol + 2][aRow] = av.z;
            As[aCol + 3][aRow] = av.w;
        }
        // load B tile (16 x 64)
        {
            int bRow = tid >> 4;
            int bCol = (tid & 15) << 2;
            *(float4*)&Bs[bRow][bCol] =
                *(const float4*)(W + (size_t)(k0 + bRow) * 256 + n0 + bCol);
        }
        __syncthreads();

#pragma unroll
        for (int kk = 0; kk < 16; kk++) {
            float4 b4 = *(float4*)&Bs[kk][tx << 2];
            float4 a0 = *(float4*)&As[kk][ty << 3];
            float4 a1 = *(float4*)&As[kk][(ty << 3) + 4];
            float a[8] = {a0.x, a0.y, a0.z, a0.w, a1.x, a1.y, a1.z, a1.w};
            float b[4] = {b4.x, b4.y, b4.z, b4.w};
#pragma unroll
            for (int i = 0; i < 8; i++)
#pragma unroll
                for (int j = 0; j < 4; j++)
                    acc[i][j] = fmaf(a[i], b[j], acc[i][j]);
        }
        __syncthreads();
    }

    float4 bb = *(const float4*)(bias + n0 + (tx << 2));
#pragma unroll
    for (int i = 0; i < 8; i++) {
        int row = m0 + (ty << 3) + i;
        if (row < M) {
            float4 o = make_float4(acc[i][0] + bb.x, acc[i][1] + bb.y,
                                   acc[i][2] + bb.z, acc[i][3] + bb.w);
            *(float4*)(C + (size_t)row * 256 + n0 + (tx << 2)) = o;
        }
    }
}

// ---------------- CSR build ----------------
__global__ void zero_counts_kernel(int n) {
    int i = blockIdx.x * blockDim.x + threadIdx.x;
    if (i < n) g_counts[i] = 0;
}

// edge_index is int32 (JAX silently downcasts int64 without x64 mode):
// ei[e] = src, ei[E + e] = dst
__global__ void hist_kernel(const int* __restrict__ ei, int E) {
    int e = blockIdx.x * blockDim.x + threadIdx.x;
    if (e < E) {
        int d = ei[E + e];
        atomicAdd(&g_counts[d], 1);
    }
}

// single-block exclusive scan over counts -> offsets, cursor
__global__ void scan_kernel(int n) {
    __shared__ int sh[1024];
    __shared__ int carry;
    int t = threadIdx.x;
    if (t == 0) carry = 0;
    __syncthreads();
    for (int base = 0; base < n; base += 1024) {
        int i = base + t;
        int v = (i < n) ? g_counts[i] : 0;
        sh[t] = v;
        __syncthreads();
        for (int off = 1; off < 1024; off <<= 1) {
            int add = (t >= off) ? sh[t - off] : 0;
            __syncthreads();
            sh[t] += add;
            __syncthreads();
        }
        int excl = sh[t] - v;
        if (i < n) { g_off[i] = carry + excl; g_cur[i] = carry + excl; }
        int total = sh[1023];
        __syncthreads();
        if (t == 0) carry += total;
        __syncthreads();
    }
    if (t == 0) g_off[n] = carry;
}

__global__ void scatter_kernel(const int* __restrict__ ei, int E) {
    int e = blockIdx.x * blockDim.x + threadIdx.x;
    if (e < E) {
        int d = ei[E + e];
        int p = atomicAdd(&g_cur[d], 1);
        g_perm[p] = e;
    }
}

// ---------------- attention + epilogue: one warp per dst node ----------------
// lane -> (head = lane>>2, sub = lane&3), covers d-range [sub*8, sub*8+8)
__global__ __launch_bounds__(256) void attn_kernel(
    const int* __restrict__ ei, const float* __restrict__ x,
    const float* __restrict__ gamma, const float* __restrict__ beta,
    float* __restrict__ out, int n)
{
    int gw = (blockIdx.x * blockDim.x + threadIdx.x) >> 5;
    if (gw >= n) return;
    int lane = threadIdx.x & 31;
    int col0 = ((lane >> 2) << 5) + ((lane & 3) << 3);   // h*32 + sub*8
    size_t rowbase = (size_t)gw * HIDD;

    float qf[8];
    {
        float4 q0 = *(const float4*)(g_q + rowbase + col0);
        float4 q1 = *(const float4*)(g_q + rowbase + col0 + 4);
        qf[0] = q0.x; qf[1] = q0.y; qf[2] = q0.z; qf[3] = q0.w;
        qf[4] = q1.x; qf[5] = q1.y; qf[6] = q1.z; qf[7] = q1.w;
    }

    float m = -FLT_MAX, l = 0.f;
    float acc[8];
#pragma unroll
    for (int j = 0; j < 8; j++) acc[j] = 0.f;

    int beg = g_off[gw], end = g_off[gw + 1];
    int cnt = end - beg;
    const float rsD = 0.17677669529663689f;   // 1/sqrt(32)

    int prev = -1;
    for (int it = 0; it < cnt; it++) {
        // deterministic processing order: next-smallest edge id in segment
        int mn = 0x7fffffff;
        for (int t = lane; t < cnt; t += 32) {
            int ev = g_perm[beg + t];
            if (ev > prev && ev < mn) mn = ev;
        }
#pragma unroll
        for (int o = 16; o; o >>= 1)
            mn = min(mn, __shfl_xor_sync(0xffffffffu, mn, o));
        prev = mn;

        size_t sbase = (size_t)ei[mn] * HIDD + col0;   // src node row
        float4 k0 = *(const float4*)(g_k + sbase);
        float4 k1 = *(const float4*)(g_k + sbase + 4);
        float d = qf[0] * k0.x + qf[1] * k0.y + qf[2] * k0.z + qf[3] * k0.w
                + qf[4] * k1.x + qf[5] * k1.y + qf[6] * k1.z + qf[7] * k1.w;
        d += __shfl_xor_sync(0xffffffffu, d, 1);
        d += __shfl_xor_sync(0xffffffffu, d, 2);
        float logit = d * rsD;

        float mnew = fmaxf(m, logit);
        float sc   = __expf(m - mnew);       // m = -FLT_MAX -> 0 on first edge
        float p    = __expf(logit - mnew);
        m = mnew;
        l = l * sc + p;

        float4 v0 = *(const float4*)(g_v + sbase);
        float4 v1 = *(const float4*)(g_v + sbase + 4);
        acc[0] = acc[0] * sc + p * v0.x;
        acc[1] = acc[1] * sc + p * v0.y;
        acc[2] = acc[2] * sc + p * v0.z;
        acc[3] = acc[3] * sc + p * v0.w;
        acc[4] = acc[4] * sc + p * v1.x;
        acc[5] = acc[5] * sc + p * v1.y;
        acc[6] = acc[6] * sc + p * v1.z;
        acc[7] = acc[7] * sc + p * v1.w;
    }

    float inv = (l > 0.f) ? (1.f / l) : 0.f;

    // epilogue: + skip, exact GELU, residual, LayerNorm
    const float* xr = x      + rowbase + col0;
    const float* sk = g_skip + rowbase + col0;
    float y[8];
    float s1 = 0.f, s2 = 0.f;
#pragma unroll
    for (int j = 0; j < 8; j++) {
        float o  = acc[j] * inv + sk[j];
        float g  = 0.5f * o * (1.f + erff(o * 0.70710678118654752f));
        float yy = xr[j] + g;
        y[j] = yy;
        s1 += yy;
        s2 += yy * yy;
    }
#pragma unroll
    for (int o = 16; o; o >>= 1) {
        s1 += __shfl_xor_sync(0xffffffffu, s1, o);
        s2 += __shfl_xor_sync(0xffffffffu, s2, o);
    }
    float mean = s1 * (1.f / 256.f);
    float var  = s2 * (1.f / 256.f) - mean * mean;
    float istd = rsqrtf(var + 1e-5f);
#pragma unroll
    for (int j = 0; j < 8; j++)
        out[rowbase + col0 + j] = (y[j] - mean) * istd * gamma[col0 + j] + beta[col0 + j];
}

// ---------------- launch ----------------
extern "C" void kernel_launch(void* const* d_in, const int* in_sizes, int n_in,
                              void* d_out, int out_size)
{
    const float* x     = (const float*)d_in[0];
    const int*   ei    = (const int*)d_in[1];      // int32! (2, E) row-major
    const float* Wq    = (const float*)d_in[2];
    const float* bq    = (const float*)d_in[3];
    const float* Wk    = (const float*)d_in[4];
    const float* bk    = (const float*)d_in[5];
    const float* Wv    = (const float*)d_in[6];
    const float* bv    = (const float*)d_in[7];
    const float* Wsk   = (const float*)d_in[8];
    const float* bsk   = (const float*)d_in[9];
    const float* gamma = (const float*)d_in[10];
    const float* beta  = (const float*)d_in[11];
    float* out = (float*)d_out;

    int n = in_sizes[0] / HIDD;     // 50000
    int E = in_sizes[1] / 2;        // 800000

    dim3 gemm_grid((n + 127) / 128, 4);
    sgemm_bias<<<gemm_grid, 256>>>(x, Wq,  bq,  0, n);
    sgemm_bias<<<gemm_grid, 256>>>(x, Wk,  bk,  1, n);
    sgemm_bias<<<gemm_grid, 256>>>(x, Wv,  bv,  2, n);
    sgemm_bias<<<gemm_grid, 256>>>(x, Wsk, bsk, 3, n);

    zero_counts_kernel<<<(n + 255) / 256, 256>>>(n);
    hist_kernel<<<(E + 255) / 256, 256>>>(ei, E);
    scan_kernel<<<1, 1024>>>(n);
    scatter_kernel<<<(E + 255) / 256, 256>>>(ei, E);

    attn_kernel<<<(n * 32 + 255) / 256, 256>>>(ei, x, gamma, beta, out, n);
}

// round 9
// speedup vs baseline: 1.6286x; 1.6286x over previous
#include <cuda_runtime.h>
#include <cuda_bf16.h>
#include <math.h>
#include <float.h>
#include <stdint.h>

#define NN   50000
#define EE   800000
#define HIDD 256

// ---------------- scratch (no allocations allowed) ----------------
__device__ float g_q   [(size_t)NN * HIDD];
__device__ float g_k   [(size_t)NN * HIDD];
__device__ float g_v   [(size_t)NN * HIDD];
__device__ float g_skip[(size_t)NN * HIDD];
__device__ int   g_counts[NN];
__device__ int   g_off[NN + 1];
__device__ int   g_cur[NN];
__device__ int   g_perm[EE];

// bf16 split operands
__device__ __align__(16) __nv_bfloat16 g_xhi[(size_t)NN * HIDD];
__device__ __align__(16) __nv_bfloat16 g_xlo[(size_t)NN * HIDD];
// W transposed: wt[which][n][k] = W[k][n]
__device__ __align__(16) __nv_bfloat16 g_wthi[4 * HIDD * HIDD];
__device__ __align__(16) __nv_bfloat16 g_wtlo[4 * HIDD * HIDD];

// ======================= helpers =======================
__device__ __forceinline__ uint32_t smem_u32(const void* p) {
    uint32_t a;
    asm("{ .reg .u64 t; cvta.to.shared.u64 t, %1; cvt.u32.u64 %0, t; }" : "=r"(a) : "l"(p));
    return a;
}

__device__ __forceinline__ void ldmat4(uint32_t* r, uint32_t addr) {
    asm volatile("ldmatrix.sync.aligned.m8n8.x4.shared.b16 {%0,%1,%2,%3}, [%4];"
                 : "=r"(r[0]), "=r"(r[1]), "=r"(r[2]), "=r"(r[3]) : "r"(addr));
}

__device__ __forceinline__ void mma16816(float* d, const uint32_t* a, const uint32_t* b) {
    asm volatile(
        "mma.sync.aligned.m16n8k16.row.col.f32.bf16.bf16.f32 "
        "{%0,%1,%2,%3}, {%4,%5,%6,%7}, {%8,%9}, {%0,%1,%2,%3};"
        : "+f"(d[0]), "+f"(d[1]), "+f"(d[2]), "+f"(d[3])
        : "r"(a[0]), "r"(a[1]), "r"(a[2]), "r"(a[3]), "r"(b[0]), "r"(b[1]));
}

// ======================= conversion kernels =======================
__global__ void convert_x_kernel(const float* __restrict__ x, int total4) {
    int i = blockIdx.x * blockDim.x + threadIdx.x;
    if (i >= total4) return;
    float4 v = *(const float4*)(x + (size_t)i * 4);
    __nv_bfloat16 h0 = __float2bfloat16_rn(v.x);
    __nv_bfloat16 h1 = __float2bfloat16_rn(v.y);
    __nv_bfloat16 h2 = __float2bfloat16_rn(v.z);
    __nv_bfloat16 h3 = __float2bfloat16_rn(v.w);
    __nv_bfloat16 l0 = __float2bfloat16_rn(v.x - __bfloat162float(h0));
    __nv_bfloat16 l1 = __float2bfloat16_rn(v.y - __bfloat162float(h1));
    __nv_bfloat16 l2 = __float2bfloat16_rn(v.z - __bfloat162float(h2));
    __nv_bfloat16 l3 = __float2bfloat16_rn(v.w - __bfloat162float(h3));
    __nv_bfloat162* ph = (__nv_bfloat162*)(g_xhi + (size_t)i * 4);
    __nv_bfloat162* pl = (__nv_bfloat162*)(g_xlo + (size_t)i * 4);
    ph[0] = __nv_bfloat162(h0, h1); ph[1] = __nv_bfloat162(h2, h3);
    pl[0] = __nv_bfloat162(l0, l1); pl[1] = __nv_bfloat162(l2, l3);
}

// transpose + split weights: wt[which][n*256+k] = W_which[k*256+n]
__global__ void convert_w_kernel(const float* __restrict__ Wq, const float* __restrict__ Wk,
                                 const float* __restrict__ Wv, const float* __restrict__ Ws) {
    int i = blockIdx.x * blockDim.x + threadIdx.x;
    if (i >= 4 * HIDD * HIDD) return;
    int which = i >> 16;
    int r = i & 0xFFFF;
    int k = r >> 8, n = r & 255;
    const float* W = (which == 0) ? Wq : (which == 1) ? Wk : (which == 2) ? Wv : Ws;
    float v = W[k * HIDD + n];
    __nv_bfloat16 h = __float2bfloat16_rn(v);
    __nv_bfloat16 l = __float2bfloat16_rn(v - __bfloat162float(h));
    g_wthi[which * HIDD * HIDD + n * HIDD + k] = h;
    g_wtlo[which * HIDD * HIDD + n * HIDD + k] = l;
}

// ======================= HMMA GEMM (mma.sync bf16, 3-pass split) =======================
// CTA: 128(M) x 128(N) tile of C[which]. grid (ceil(M/128), 2, 4). 256 threads.
// SMEM: 4 tiles of 128 rows x 32 k-elems (64B) at 80B pitch (conflict-free ldmatrix).
#define PITCH 80
#define AH_OFF 0
#define AL_OFF 10240
#define BH_OFF 20480
#define BL_OFF 30720

__global__ __launch_bounds__(256) void gemm_hmma_kernel(
    const float* __restrict__ bq, const float* __restrict__ bk,
    const float* __restrict__ bv, const float* __restrict__ bs, int M)
{
    __shared__ __align__(128) char smem[40960];
    uint32_t sb = smem_u32(smem);
    int tid = threadIdx.x, lane = tid & 31, wid = tid >> 5;
    int m0 = blockIdx.x * 128;
    int ntile = blockIdx.y;
    int which = blockIdx.z;
    int wm = wid & 3, wn = wid >> 2;

    const __nv_bfloat16* wtH = g_wthi + which * HIDD * HIDD;
    const __nv_bfloat16* wtL = g_wtlo + which * HIDD * HIDD;
    float* C = (which == 0) ? g_q : (which == 1) ? g_k : (which == 2) ? g_v : g_skip;
    const float* bias = (which == 0) ? bq : (which == 1) ? bk : (which == 2) ? bv : bs;

    float acc[2][8][4];
#pragma unroll
    for (int mt = 0; mt < 2; mt++)
#pragma unroll
        for (int nt = 0; nt < 8; nt++)
#pragma unroll
            for (int j = 0; j < 4; j++) acc[mt][nt][j] = 0.f;

#pragma unroll 1
    for (int kc = 0; kc < 8; kc++) {
        int k0 = kc * 32;
        // ---- stage tiles ----
#pragma unroll
        for (int it = 0; it < 2; it++) {
            int i = tid + it * 256;          // 0..511
            int r = i >> 2, c = i & 3;       // row 0..127, 16B chunk 0..3
            uint32_t so = (uint32_t)(r * PITCH + c * 16);
            uint4 vh = make_uint4(0, 0, 0, 0), vl = make_uint4(0, 0, 0, 0);
            if (m0 + r < M) {
                size_t src = (size_t)(m0 + r) * HIDD + k0 + c * 8;
                vh = *(const uint4*)(g_xhi + src);
                vl = *(const uint4*)(g_xlo + src);
            }
            *(uint4*)(smem + AH_OFF + so) = vh;
            *(uint4*)(smem + AL_OFF + so) = vl;
            size_t bsrc = (size_t)(ntile * 128 + r) * HIDD + k0 + c * 8;
            *(uint4*)(smem + BH_OFF + so) = *(const uint4*)(wtH + bsrc);
            *(uint4*)(smem + BL_OFF + so) = *(const uint4*)(wtL + bsrc);
        }
        __syncthreads();

#pragma unroll
        for (int s = 0; s < 2; s++) {
            uint32_t ah[2][4], al[2][4];
#pragma unroll
            for (int mt = 0; mt < 2; mt++) {
                uint32_t row = (uint32_t)(wm * 32 + mt * 16 + (lane & 15));
                uint32_t off = row * PITCH + (uint32_t)(s * 2 + (lane >> 4)) * 16;
                ldmat4(ah[mt], sb + AH_OFF + off);
                ldmat4(al[mt], sb + AL_OFF + off);
            }
#pragma unroll
            for (int ng = 0; ng < 4; ng++) {
                uint32_t nrow = (uint32_t)(wn * 64 + ng * 16 + (lane & 7) + ((lane >> 4) << 3));
                uint32_t off = nrow * PITCH + (uint32_t)(s * 2 + ((lane >> 3) & 1)) * 16;
                uint32_t bh[4], bl[4];
                ldmat4(bh, sb + BH_OFF + off);
                ldmat4(bl, sb + BL_OFF + off);
#pragma unroll
                for (int half = 0; half < 2; half++) {
                    int nt = ng * 2 + half;
#pragma unroll
                    for (int mt = 0; mt < 2; mt++) {
                        mma16816(acc[mt][nt], ah[mt], &bh[half * 2]);
                        mma16816(acc[mt][nt], al[mt], &bh[half * 2]);
                        mma16816(acc[mt][nt], ah[mt], &bl[half * 2]);
                    }
                }
            }
        }
        __syncthreads();
    }

    // ---- epilogue: store + bias ----
    int colbase = ntile * 128 + wn * 64;
    int rbase = m0 + wm * 32 + (lane >> 2);
#pragma unroll
    for (int mt = 0; mt < 2; mt++) {
#pragma unroll
        for (int nt = 0; nt < 8; nt++) {
            int col = colbase + nt * 8 + (lane & 3) * 2;
            float b0 = bias[col], b1 = bias[col + 1];
            int r0 = rbase + mt * 16;
            if (r0 < M) {
                float2 o = make_float2(acc[mt][nt][0] + b0, acc[mt][nt][1] + b1);
                *(float2*)(C + (size_t)r0 * HIDD + col) = o;
            }
            if (r0 + 8 < M) {
                float2 o = make_float2(acc[mt][nt][2] + b0, acc[mt][nt][3] + b1);
                *(float2*)(C + (size_t)(r0 + 8) * HIDD + col) = o;
            }
        }
    }
}

// ---------------- CSR build ----------------
__global__ void zero_counts_kernel(int n) {
    int i = blockIdx.x * blockDim.x + threadIdx.x;
    if (i < n) g_counts[i] = 0;
}

__global__ void hist_kernel(const int* __restrict__ ei, int E) {
    int e = blockIdx.x * blockDim.x + threadIdx.x;
    if (e < E) atomicAdd(&g_counts[ei[E + e]], 1);
}

__global__ void scan_kernel(int n) {
    __shared__ int sh[1024];
    __shared__ int carry;
    int t = threadIdx.x;
    if (t == 0) carry = 0;
    __syncthreads();
    for (int base = 0; base < n; base += 1024) {
        int i = base + t;
        int v = (i < n) ? g_counts[i] : 0;
        sh[t] = v;
        __syncthreads();
        for (int off = 1; off < 1024; off <<= 1) {
            int add = (t >= off) ? sh[t - off] : 0;
            __syncthreads();
            sh[t] += add;
            __syncthreads();
        }
        int excl = sh[t] - v;
        if (i < n) { g_off[i] = carry + excl; g_cur[i] = carry + excl; }
        int total = sh[1023];
        __syncthreads();
        if (t == 0) carry += total;
        __syncthreads();
    }
    if (t == 0) g_off[n] = carry;
}

__global__ void scatter_kernel(const int* __restrict__ ei, int E) {
    int e = blockIdx.x * blockDim.x + threadIdx.x;
    if (e < E) {
        int d = ei[E + e];
        int p = atomicAdd(&g_cur[d], 1);
        g_perm[p] = e;
    }
}

// sort each CSR segment by edge id -> deterministic order regardless of the
// nondeterministic atomic scatter. One thread per node; insertion sort (deg~16).
__global__ void sort_kernel(int n) {
    int i = blockIdx.x * blockDim.x + threadIdx.x;
    if (i >= n) return;
    int beg = g_off[i], end = g_off[i + 1];
    for (int a = beg + 1; a < end; a++) {
        int v = g_perm[a];
        int b = a - 1;
        while (b >= beg && g_perm[b] > v) { g_perm[b + 1] = g_perm[b]; b--; }
        g_perm[b + 1] = v;
    }
}

// ---------------- attention + epilogue: one warp per dst node ----------------
// Edges pre-sorted in g_perm -> simple sequential walk, deterministic.
__global__ __launch_bounds__(256) void attn_kernel(
    const int* __restrict__ ei, const float* __restrict__ x,
    const float* __restrict__ gamma, const float* __restrict__ beta,
    float* __restrict__ out, int n)
{
    int gw = (blockIdx.x * blockDim.x + threadIdx.x) >> 5;
    if (gw >= n) return;
    int lane = threadIdx.x & 31;
    int col0 = ((lane >> 2) << 5) + ((lane & 3) << 3);   // h*32 + sub*8
    size_t rowbase = (size_t)gw * HIDD;

    float qf[8];
    {
        float4 q0 = *(const float4*)(g_q + rowbase + col0);
        float4 q1 = *(const float4*)(g_q + rowbase + col0 + 4);
        qf[0] = q0.x; qf[1] = q0.y; qf[2] = q0.z; qf[3] = q0.w;
        qf[4] = q1.x; qf[5] = q1.y; qf[6] = q1.z; qf[7] = q1.w;
    }

    float m = -FLT_MAX, l = 0.f;
    float acc[8];
#pragma unroll
    for (int j = 0; j < 8; j++) acc[j] = 0.f;

    int beg = g_off[gw], end = g_off[gw + 1];
    const float rsD = 0.17677669529663689f;   // 1/sqrt(32)

    // prefetch first src index
    int src_next = (beg < end) ? ei[g_perm[beg]] : 0;
#pragma unroll 1
    for (int p_ = beg; p_ < end; p_++) {
        int src = src_next;
        if (p_ + 1 < end) src_next = ei[g_perm[p_ + 1]];

        size_t sbase = (size_t)src * HIDD + col0;
        float4 k0 = *(const float4*)(g_k + sbase);
        float4 k1 = *(const float4*)(g_k + sbase + 4);
        float4 v0 = *(const float4*)(g_v + sbase);
        float4 v1 = *(const float4*)(g_v + sbase + 4);

        float d = qf[0] * k0.x + qf[1] * k0.y + qf[2] * k0.z + qf[3] * k0.w
                + qf[4] * k1.x + qf[5] * k1.y + qf[6] * k1.z + qf[7] * k1.w;
        d += __shfl_xor_sync(0xffffffffu, d, 1);
        d += __shfl_xor_sync(0xffffffffu, d, 2);
        float logit = d * rsD;

        float mnew = fmaxf(m, logit);
        float sc   = __expf(m - mnew);       // first edge: exp(-inf) = 0
        float p    = __expf(logit - mnew);
        m = mnew;
        l = l * sc + p;

        acc[0] = acc[0] * sc + p * v0.x;
        acc[1] = acc[1] * sc + p * v0.y;
        acc[2] = acc[2] * sc + p * v0.z;
        acc[3] = acc[3] * sc + p * v0.w;
        acc[4] = acc[4] * sc + p * v1.x;
        acc[5] = acc[5] * sc + p * v1.y;
        acc[6] = acc[6] * sc + p * v1.z;
        acc[7] = acc[7] * sc + p * v1.w;
    }

    float inv = (l > 0.f) ? (1.f / l) : 0.f;

    const float* xr = x      + rowbase + col0;
    const float* sk = g_skip + rowbase + col0;
    float y[8];
    float s1 = 0.f, s2 = 0.f;
#pragma unroll
    for (int j = 0; j < 8; j++) {
        float o  = acc[j] * inv + sk[j];
        float g  = 0.5f * o * (1.f + erff(o * 0.70710678118654752f));
        float yy = xr[j] + g;
        y[j] = yy;
        s1 += yy;
        s2 += yy * yy;
    }
#pragma unroll
    for (int o = 16; o; o >>= 1) {
        s1 += __shfl_xor_sync(0xffffffffu, s1, o);
        s2 += __shfl_xor_sync(0xffffffffu, s2, o);
    }
    float mean = s1 * (1.f / 256.f);
    float var  = s2 * (1.f / 256.f) - mean * mean;
    float istd = rsqrtf(var + 1e-5f);
#pragma unroll
    for (int j = 0; j < 8; j++)
        out[rowbase + col0 + j] = (y[j] - mean) * istd * gamma[col0 + j] + beta[col0 + j];
}

// ---------------- launch ----------------
extern "C" void kernel_launch(void* const* d_in, const int* in_sizes, int n_in,
                              void* d_out, int out_size)
{
    const float* x     = (const float*)d_in[0];
    const int*   ei    = (const int*)d_in[1];      // int32 (2, E) row-major
    const float* Wq    = (const float*)d_in[2];
    const float* bq    = (const float*)d_in[3];
    const float* Wk    = (const float*)d_in[4];
    const float* bk    = (const float*)d_in[5];
    const float* Wv    = (const float*)d_in[6];
    const float* bv    = (const float*)d_in[7];
    const float* Wsk   = (const float*)d_in[8];
    const float* bsk   = (const float*)d_in[9];
    const float* gamma = (const float*)d_in[10];
    const float* beta  = (const float*)d_in[11];
    float* out = (float*)d_out;

    int n = in_sizes[0] / HIDD;     // 50000
    int E = in_sizes[1] / 2;        // 800000

    int total4 = n * HIDD / 4;
    convert_x_kernel<<<(total4 + 255) / 256, 256>>>(x, total4);
    convert_w_kernel<<<(4 * HIDD * HIDD + 255) / 256, 256>>>(Wq, Wk, Wv, Wsk);

    dim3 ggrid((n + 127) / 128, 2, 4);
    gemm_hmma_kernel<<<ggrid, 256>>>(bq, bk, bv, bsk, n);

    zero_counts_kernel<<<(n + 255) / 256, 256>>>(n);
    hist_kernel<<<(E + 255) / 256, 256>>>(ei, E);
    scan_kernel<<<1, 1024>>>(n);
    scatter_kernel<<<(E + 255) / 256, 256>>>(ei, E);
    sort_kernel<<<(n + 255) / 256, 256>>>(n);

    attn_kernel<<<(n * 32 + 255) / 256, 256>>>(ei, x, gamma, beta, out, n);
}

// round 12
// speedup vs baseline: 1.8828x; 1.1561x over previous
#include <cuda_runtime.h>
#include <cuda_bf16.h>
#include <math.h>
#include <float.h>
#include <stdint.h>

#define NN   50000
#define EE   800000
#define HIDD 256

// ---------------- scratch (no allocations allowed) ----------------
__device__ float g_q   [(size_t)NN * HIDD];
__device__ float g_skip[(size_t)NN * HIDD];
__device__ __align__(16) __nv_bfloat16 g_kb[(size_t)NN * HIDD];   // k in bf16
__device__ __align__(16) __nv_bfloat16 g_vb[(size_t)NN * HIDD];   // v in bf16
__device__ int   g_counts[NN];
__device__ int   g_off[NN + 1];
__device__ int   g_cur[NN];
__device__ int   g_perm[EE];

// bf16 split operands
__device__ __align__(16) __nv_bfloat16 g_xhi[(size_t)NN * HIDD];
__device__ __align__(16) __nv_bfloat16 g_xlo[(size_t)NN * HIDD];
// W transposed: wt[which][n][k] = W[k][n]
__device__ __align__(16) __nv_bfloat16 g_wthi[4 * HIDD * HIDD];
__device__ __align__(16) __nv_bfloat16 g_wtlo[4 * HIDD * HIDD];

// ======================= helpers =======================
__device__ __forceinline__ uint32_t smem_u32(const void* p) {
    uint32_t a;
    asm("{ .reg .u64 t; cvta.to.shared.u64 t, %1; cvt.u32.u64 %0, t; }" : "=r"(a) : "l"(p));
    return a;
}

__device__ __forceinline__ void ldmat4(uint32_t* r, uint32_t addr) {
    asm volatile("ldmatrix.sync.aligned.m8n8.x4.shared.b16 {%0,%1,%2,%3}, [%4];"
                 : "=r"(r[0]), "=r"(r[1]), "=r"(r[2]), "=r"(r[3]) : "r"(addr));
}

__device__ __forceinline__ void mma16816(float* d, const uint32_t* a, const uint32_t* b) {
    asm volatile(
        "mma.sync.aligned.m16n8k16.row.col.f32.bf16.bf16.f32 "
        "{%0,%1,%2,%3}, {%4,%5,%6,%7}, {%8,%9}, {%0,%1,%2,%3};"
        : "+f"(d[0]), "+f"(d[1]), "+f"(d[2]), "+f"(d[3])
        : "r"(a[0]), "r"(a[1]), "r"(a[2]), "r"(a[3]), "r"(b[0]), "r"(b[1]));
}

__device__ __forceinline__ void cpa16(uint32_t dst, const void* src, int size) {
    asm volatile("cp.async.cg.shared.global [%0], [%1], 16, %2;"
                 :: "r"(dst), "l"(src), "r"(size) : "memory");
}
#define CP_COMMIT() asm volatile("cp.async.commit_group;" ::: "memory")
#define CP_WAIT1()  asm volatile("cp.async.wait_group 1;" ::: "memory")
#define CP_WAIT0()  asm volatile("cp.async.wait_group 0;" ::: "memory")

// ======================= conversion kernels =======================
__global__ void convert_x_kernel(const float* __restrict__ x, int total4) {
    int i = blockIdx.x * blockDim.x + threadIdx.x;
    if (i >= total4) return;
    float4 v = *(const float4*)(x + (size_t)i * 4);
    __nv_bfloat16 h0 = __float2bfloat16_rn(v.x);
    __nv_bfloat16 h1 = __float2bfloat16_rn(v.y);
    __nv_bfloat16 h2 = __float2bfloat16_rn(v.z);
    __nv_bfloat16 h3 = __float2bfloat16_rn(v.w);
    __nv_bfloat16 l0 = __float2bfloat16_rn(v.x - __bfloat162float(h0));
    __nv_bfloat16 l1 = __float2bfloat16_rn(v.y - __bfloat162float(h1));
    __nv_bfloat16 l2 = __float2bfloat16_rn(v.z - __bfloat162float(h2));
    __nv_bfloat16 l3 = __float2bfloat16_rn(v.w - __bfloat162float(h3));
    __nv_bfloat162* ph = (__nv_bfloat162*)(g_xhi + (size_t)i * 4);
    __nv_bfloat162* pl = (__nv_bfloat162*)(g_xlo + (size_t)i * 4);
    ph[0] = __nv_bfloat162(h0, h1); ph[1] = __nv_bfloat162(h2, h3);
    pl[0] = __nv_bfloat162(l0, l1); pl[1] = __nv_bfloat162(l2, l3);
}

// transpose + split weights: wt[which][n*256+k] = W_which[k*256+n]
__global__ void convert_w_kernel(const float* __restrict__ Wq, const float* __restrict__ Wk,
                                 const float* __restrict__ Wv, const float* __restrict__ Ws) {
    int i = blockIdx.x * blockDim.x + threadIdx.x;
    if (i >= 4 * HIDD * HIDD) return;
    int which = i >> 16;
    int r = i & 0xFFFF;
    int k = r >> 8, n = r & 255;
    const float* W = (which == 0) ? Wq : (which == 1) ? Wk : (which == 2) ? Wv : Ws;
    float v = W[k * HIDD + n];
    __nv_bfloat16 h = __float2bfloat16_rn(v);
    __nv_bfloat16 l = __float2bfloat16_rn(v - __bfloat162float(h));
    g_wthi[which * HIDD * HIDD + n * HIDD + k] = h;
    g_wtlo[which * HIDD * HIDD + n * HIDD + k] = l;
}

// ======================= HMMA GEMM (mma.sync bf16, 3-pass split, cp.async 2-buffer) =====
// CTA: 128(M) x 128(N) tile of C[which]. grid (ceil(M/128), 2, 4). 256 threads.
// Per buffer: 4 tiles of 128 rows x 32 k-elems (64B) at 80B pitch. 2 buffers = 80 KB.
#define PITCH  80
#define AH_OFF 0
#define AL_OFF 10240
#define BH_OFF 20480
#define BL_OFF 30720
#define BUFSZ  40960

__global__ __launch_bounds__(256) void gemm_hmma_kernel(
    const float* __restrict__ bq, const float* __restrict__ bk,
    const float* __restrict__ bv, const float* __restrict__ bs, int M)
{
    extern __shared__ __align__(128) char smem[];
    uint32_t sb = smem_u32(smem);
    int tid = threadIdx.x, lane = tid & 31, wid = tid >> 5;
    int m0 = blockIdx.x * 128;
    int ntile = blockIdx.y;
    int which = blockIdx.z;
    int wm = wid & 3, wn = wid >> 2;

    const __nv_bfloat16* wtH = g_wthi + which * HIDD * HIDD;
    const __nv_bfloat16* wtL = g_wtlo + which * HIDD * HIDD;
    const float* bias = (which == 0) ? bq : (which == 1) ? bk : (which == 2) ? bv : bs;

    float acc[2][8][4];
#pragma unroll
    for (int mt = 0; mt < 2; mt++)
#pragma unroll
        for (int nt = 0; nt < 8; nt++)
#pragma unroll
            for (int j = 0; j < 4; j++) acc[mt][nt][j] = 0.f;

    // stage chunk kc into buffer bb (base address sb + bb*BUFSZ)
    auto stage = [&](int bb, int kc) {
        int k0 = kc * 32;
        uint32_t base = sb + (uint32_t)bb * BUFSZ;
#pragma unroll
        for (int it = 0; it < 2; it++) {
            int i = tid + it * 256;          // 0..511
            int r = i >> 2, c = i & 3;       // row 0..127, 16B chunk 0..3
            uint32_t so = (uint32_t)(r * PITCH + c * 16);
            int row = m0 + r;
            int ok = (row < M) ? 16 : 0;
            int srow = (row < M) ? row : 0;
            size_t asrc = (size_t)srow * HIDD + k0 + c * 8;
            cpa16(base + AH_OFF + so, g_xhi + asrc, ok);
            cpa16(base + AL_OFF + so, g_xlo + asrc, ok);
            size_t bsrc = (size_t)(ntile * 128 + r) * HIDD + k0 + c * 8;
            cpa16(base + BH_OFF + so, wtH + bsrc, 16);
            cpa16(base + BL_OFF + so, wtL + bsrc, 16);
        }
        CP_COMMIT();
    };

    stage(0, 0);
#pragma unroll 1
    for (int kc = 0; kc < 8; kc++) {
        int buf = kc & 1;
        if (kc < 7) { stage(buf ^ 1, kc + 1); CP_WAIT1(); }
        else        { CP_WAIT0(); }
        __syncthreads();

        uint32_t bbase = sb + (uint32_t)buf * BUFSZ;
#pragma unroll
        for (int s = 0; s < 2; s++) {
            uint32_t ah[2][4], al[2][4];
#pragma unroll
            for (int mt = 0; mt < 2; mt++) {
                uint32_t row = (uint32_t)(wm * 32 + mt * 16 + (lane & 15));
                uint32_t off = row * PITCH + (uint32_t)(s * 2 + (lane >> 4)) * 16;
                ldmat4(ah[mt], bbase + AH_OFF + off);
                ldmat4(al[mt], bbase + AL_OFF + off);
            }
#pragma unroll
            for (int ng = 0; ng < 4; ng++) {
                uint32_t nrow = (uint32_t)(wn * 64 + ng * 16 + (lane & 7) + ((lane >> 4) << 3));
                uint32_t off = nrow * PITCH + (uint32_t)(s * 2 + ((lane >> 3) & 1)) * 16;
                uint32_t bh[4], bl[4];
                ldmat4(bh, bbase + BH_OFF + off);
                ldmat4(bl, bbase + BL_OFF + off);
#pragma unroll
                for (int half = 0; half < 2; half++) {
                    int nt = ng * 2 + half;
#pragma unroll
                    for (int mt = 0; mt < 2; mt++) {
                        mma16816(acc[mt][nt], ah[mt], &bh[half * 2]);
                        mma16816(acc[mt][nt], al[mt], &bh[half * 2]);
                        mma16816(acc[mt][nt], ah[mt], &bl[half * 2]);
                    }
                }
            }
        }
        __syncthreads();
    }

    // ---- epilogue: +bias; q/skip -> fp32, k/v -> bf16 ----
    int colbase = ntile * 128 + wn * 64;
    int rbase = m0 + wm * 32 + (lane >> 2);
    bool is_bf16 = (which == 1) || (which == 2);
    float* Cf = (which == 0) ? g_q : g_skip;
    __nv_bfloat16* Cb = (which == 1) ? g_kb : g_vb;
#pragma unroll
    for (int mt = 0; mt < 2; mt++) {
#pragma unroll
        for (int nt = 0; nt < 8; nt++) {
            int col = colbase + nt * 8 + (lane & 3) * 2;
            float b0 = bias[col], b1 = bias[col + 1];
            int r0 = rbase + mt * 16;
            float v00 = acc[mt][nt][0] + b0, v01 = acc[mt][nt][1] + b1;
            float v10 = acc[mt][nt][2] + b0, v11 = acc[mt][nt][3] + b1;
            if (is_bf16) {
                if (r0 < M)
                    *(__nv_bfloat162*)(Cb + (size_t)r0 * HIDD + col) =
                        __nv_bfloat162(__float2bfloat16_rn(v00), __float2bfloat16_rn(v01));
                if (r0 + 8 < M)
                    *(__nv_bfloat162*)(Cb + (size_t)(r0 + 8) * HIDD + col) =
                        __nv_bfloat162(__float2bfloat16_rn(v10), __float2bfloat16_rn(v11));
            } else {
                if (r0 < M)
                    *(float2*)(Cf + (size_t)r0 * HIDD + col) = make_float2(v00, v01);
                if (r0 + 8 < M)
                    *(float2*)(Cf + (size_t)(r0 + 8) * HIDD + col) = make_float2(v10, v11);
            }
        }
    }
}

// ---------------- CSR build ----------------
__global__ void zero_counts_kernel(int n) {
    int i = blockIdx.x * blockDim.x + threadIdx.x;
    if (i < n) g_counts[i] = 0;
}

__global__ void hist_kernel(const int* __restrict__ ei, int E) {
    int e = blockIdx.x * blockDim.x + threadIdx.x;
    if (e < E) atomicAdd(&g_counts[ei[E + e]], 1);
}

__global__ void scan_kernel(int n) {
    __shared__ int sh[1024];
    __shared__ int carry;
    int t = threadIdx.x;
    if (t == 0) carry = 0;
    __syncthreads();
    for (int base = 0; base < n; base += 1024) {
        int i = base + t;
        int v = (i < n) ? g_counts[i] : 0;
        sh[t] = v;
        __syncthreads();
        for (int off = 1; off < 1024; off <<= 1) {
            int add = (t >= off) ? sh[t - off] : 0;
            __syncthreads();
            sh[t] += add;
            __syncthreads();
        }
        int excl = sh[t] - v;
        if (i < n) { g_off[i] = carry + excl; g_cur[i] = carry + excl; }
        int total = sh[1023];
        __syncthreads();
        if (t == 0) carry += total;
        __syncthreads();
    }
    if (t == 0) g_off[n] = carry;
}

__global__ void scatter_kernel(const int* __restrict__ ei, int E) {
    int e = blockIdx.x * blockDim.x + threadIdx.x;
    if (e < E) {
        int d = ei[E + e];
        int p = atomicAdd(&g_cur[d], 1);
        g_perm[p] = e;
    }
}

// sort each CSR segment by edge id -> deterministic order regardless of the
// nondeterministic atomic scatter. One thread per node; insertion sort (deg~16).
__global__ void sort_kernel(int n) {
    int i = blockIdx.x * blockDim.x + threadIdx.x;
    if (i >= n) return;
    int beg = g_off[i], end = g_off[i + 1];
    for (int a = beg + 1; a < end; a++) {
        int v = g_perm[a];
        int b = a - 1;
        while (b >= beg && g_perm[b] > v) { g_perm[b + 1] = g_perm[b]; b--; }
        g_perm[b + 1] = v;
    }
}

// ---------------- attention + epilogue: one warp per dst node ----------------
// Edges pre-sorted in g_perm -> sequential walk, deterministic. k/v in bf16.
__global__ __launch_bounds__(256) void attn_kernel(
    const int* __restrict__ ei, const float* __restrict__ x,
    const float* __restrict__ gamma, const float* __restrict__ beta,
    float* __restrict__ out, int n)
{
    int gw = (blockIdx.x * blockDim.x + threadIdx.x) >> 5;
    if (gw >= n) return;
    int lane = threadIdx.x & 31;
    int col0 = ((lane >> 2) << 5) + ((lane & 3) << 3);   // h*32 + sub*8
    size_t rowbase = (size_t)gw * HIDD;

    float qf[8];
    {
        float4 q0 = *(const float4*)(g_q + rowbase + col0);
        float4 q1 = *(const float4*)(g_q + rowbase + col0 + 4);
        qf[0] = q0.x; qf[1] = q0.y; qf[2] = q0.z; qf[3] = q0.w;
        qf[4] = q1.x; qf[5] = q1.y; qf[6] = q1.z; qf[7] = q1.w;
    }

    float m = -FLT_MAX, l = 0.f;
    float acc[8];
#pragma unroll
    for (int j = 0; j < 8; j++) acc[j] = 0.f;

    int beg = g_off[gw], end = g_off[gw + 1];
    const float rsD = 0.17677669529663689f;   // 1/sqrt(32)

    int src_next = (beg < end) ? ei[g_perm[beg]] : 0;
#pragma unroll 1
    for (int p_ = beg; p_ < end; p_++) {
        int src = src_next;
        if (p_ + 1 < end) src_next = ei[g_perm[p_ + 1]];

        size_t sbase = (size_t)src * HIDD + col0;
        uint4 kr = *(const uint4*)(g_kb + sbase);   // 8 bf16 = 16 B
        uint4 vr = *(const uint4*)(g_vb + sbase);

        float2 k0 = __bfloat1622float2(*(__nv_bfloat162*)&kr.x);
        float2 k1 = __bfloat1622float2(*(__nv_bfloat162*)&kr.y);
        float2 k2 = __bfloat1622float2(*(__nv_bfloat162*)&kr.z);
        float2 k3 = __bfloat1622float2(*(__nv_bfloat162*)&kr.w);
        float d = qf[0] * k0.x + qf[1] * k0.y + qf[2] * k1.x + qf[3] * k1.y
                + qf[4] * k2.x + qf[5] * k2.y + qf[6] * k3.x + qf[7] * k3.y;
        d += __shfl_xor_sync(0xffffffffu, d, 1);
        d += __shfl_xor_sync(0xffffffffu, d, 2);
        float logit = d * rsD;

        float mnew = fmaxf(m, logit);
        float sc   = __expf(m - mnew);       // first edge: exp(-inf) = 0
        float p    = __expf(logit - mnew);
        m = mnew;
        l = l * sc + p;

        float2 v0 = __bfloat1622float2(*(__nv_bfloat162*)&vr.x);
        float2 v1 = __bfloat1622float2(*(__nv_bfloat162*)&vr.y);
        float2 v2 = __bfloat1622float2(*(__nv_bfloat162*)&vr.z);
        float2 v3 = __bfloat1622float2(*(__nv_bfloat162*)&vr.w);
        acc[0] = acc[0] * sc + p * v0.x;
        acc[1] = acc[1] * sc + p * v0.y;
        acc[2] = acc[2] * sc + p * v1.x;
        acc[3] = acc[3] * sc + p * v1.y;
        acc[4] = acc[4] * sc + p * v2.x;
        acc[5] = acc[5] * sc + p * v2.y;
        acc[6] = acc[6] * sc + p * v3.x;
        acc[7] = acc[7] * sc + p * v3.y;
    }

    float inv = (l > 0.f) ? (1.f / l) : 0.f;

    const float* xr = x      + rowbase + col0;
    const float* sk = g_skip + rowbase + col0;
    float y[8];
    float s1 = 0.f, s2 = 0.f;
#pragma unroll
    for (int j = 0; j < 8; j++) {
        float o  = acc[j] * inv + sk[j];
        float g  = 0.5f * o * (1.f + erff(o * 0.70710678118654752f));
        float yy = xr[j] + g;
        y[j] = yy;
        s1 += yy;
        s2 += yy * yy;
    }
#pragma unroll
    for (int o = 16; o; o >>= 1) {
        s1 += __shfl_xor_sync(0xffffffffu, s1, o);
        s2 += __shfl_xor_sync(0xffffffffu, s2, o);
    }
    float mean = s1 * (1.f / 256.f);
    float var  = s2 * (1.f / 256.f) - mean * mean;
    float istd = rsqrtf(var + 1e-5f);
#pragma unroll
    for (int j = 0; j < 8; j++)
        out[rowbase + col0 + j] = (y[j] - mean) * istd * gamma[col0 + j] + beta[col0 + j];
}

// ---------------- launch ----------------
extern "C" void kernel_launch(void* const* d_in, const int* in_sizes, int n_in,
                              void* d_out, int out_size)
{
    const float* x     = (const float*)d_in[0];
    const int*   ei    = (const int*)d_in[1];      // int32 (2, E) row-major
    const float* Wq    = (const float*)d_in[2];
    const float* bq    = (const float*)d_in[3];
    const float* Wk    = (const float*)d_in[4];
    const float* bk    = (const float*)d_in[5];
    const float* Wv    = (const float*)d_in[6];
    const float* bv    = (const float*)d_in[7];
    const float* Wsk   = (const float*)d_in[8];
    const float* bsk   = (const float*)d_in[9];
    const float* gamma = (const float*)d_in[10];
    const float* beta  = (const float*)d_in[11];
    float* out = (float*)d_out;

    int n = in_sizes[0] / HIDD;     // 50000
    int E = in_sizes[1] / 2;        // 800000

    cudaFuncSetAttribute(gemm_hmma_kernel,
                         cudaFuncAttributeMaxDynamicSharedMemorySize, 2 * BUFSZ);

    int total4 = n * HIDD / 4;
    convert_x_kernel<<<(total4 + 255) / 256, 256>>>(x, total4);
    convert_w_kernel<<<(4 * HIDD * HIDD + 255) / 256, 256>>>(Wq, Wk, Wv, Wsk);

    dim3 ggrid((n + 127) / 128, 2, 4);
    gemm_hmma_kernel<<<ggrid, 256, 2 * BUFSZ>>>(bq, bk, bv, bsk, n);

    zero_counts_kernel<<<(n + 255) / 256, 256>>>(n);
    hist_kernel<<<(E + 255) / 256, 256>>>(ei, E);
    scan_kernel<<<1, 1024>>>(n);
    scatter_kernel<<<(E + 255) / 256, 256>>>(ei, E);
    sort_kernel<<<(n + 255) / 256, 256>>>(n);

    attn_kernel<<<(n * 32 + 255) / 256, 256>>>(ei, x, gamma, beta, out, n);
}

// round 13
// speedup vs baseline: 2.2061x; 1.1717x over previous
#include <cuda_runtime.h>
#include <cuda_bf16.h>
#include <math.h>
#include <float.h>
#include <stdint.h>

#define NN   50000
#define EE   800000
#define HIDD 256

// ---------------- scratch (no allocations allowed) ----------------
__device__ float g_q   [(size_t)NN * HIDD];
__device__ float g_skip[(size_t)NN * HIDD];
__device__ __align__(16) __nv_bfloat16 g_kb[(size_t)NN * HIDD];   // k in bf16
__device__ __align__(16) __nv_bfloat16 g_vb[(size_t)NN * HIDD];   // v in bf16
__device__ int   g_counts[NN];
__device__ int   g_off[NN + 1];
__device__ int   g_cur[NN];
__device__ int   g_perm[EE];
__device__ int   g_src[EE];
__device__ int   g_bsum[64];

// bf16 split operands
__device__ __align__(16) __nv_bfloat16 g_xhi[(size_t)NN * HIDD];
__device__ __align__(16) __nv_bfloat16 g_xlo[(size_t)NN * HIDD];
// W transposed: wt[which][n][k] = W[k][n]
__device__ __align__(16) __nv_bfloat16 g_wthi[4 * HIDD * HIDD];
__device__ __align__(16) __nv_bfloat16 g_wtlo[4 * HIDD * HIDD];

// ======================= helpers =======================
__device__ __forceinline__ uint32_t smem_u32(const void* p) {
    uint32_t a;
    asm("{ .reg .u64 t; cvta.to.shared.u64 t, %1; cvt.u32.u64 %0, t; }" : "=r"(a) : "l"(p));
    return a;
}

__device__ __forceinline__ void ldmat4(uint32_t* r, uint32_t addr) {
    asm volatile("ldmatrix.sync.aligned.m8n8.x4.shared.b16 {%0,%1,%2,%3}, [%4];"
                 : "=r"(r[0]), "=r"(r[1]), "=r"(r[2]), "=r"(r[3]) : "r"(addr));
}

__device__ __forceinline__ void mma16816(float* d, const uint32_t* a, const uint32_t* b) {
    asm volatile(
        "mma.sync.aligned.m16n8k16.row.col.f32.bf16.bf16.f32 "
        "{%0,%1,%2,%3}, {%4,%5,%6,%7}, {%8,%9}, {%0,%1,%2,%3};"
        : "+f"(d[0]), "+f"(d[1]), "+f"(d[2]), "+f"(d[3])
        : "r"(a[0]), "r"(a[1]), "r"(a[2]), "r"(a[3]), "r"(b[0]), "r"(b[1]));
}

__device__ __forceinline__ void cpa16(uint32_t dst, const void* src, int size) {
    asm volatile("cp.async.cg.shared.global [%0], [%1], 16, %2;"
                 :: "r"(dst), "l"(src), "r"(size) : "memory");
}
#define CP_COMMIT() asm volatile("cp.async.commit_group;" ::: "memory")
#define CP_WAIT1()  asm volatile("cp.async.wait_group 1;" ::: "memory")
#define CP_WAIT0()  asm volatile("cp.async.wait_group 0;" ::: "memory")

// ======================= conversion kernels =======================
__global__ void convert_x_kernel(const float* __restrict__ x, int total4) {
    int i = blockIdx.x * blockDim.x + threadIdx.x;
    if (i >= total4) return;
    float4 v = *(const float4*)(x + (size_t)i * 4);
    __nv_bfloat16 h0 = __float2bfloat16_rn(v.x);
    __nv_bfloat16 h1 = __float2bfloat16_rn(v.y);
    __nv_bfloat16 h2 = __float2bfloat16_rn(v.z);
    __nv_bfloat16 h3 = __float2bfloat16_rn(v.w);
    __nv_bfloat16 l0 = __float2bfloat16_rn(v.x - __bfloat162float(h0));
    __nv_bfloat16 l1 = __float2bfloat16_rn(v.y - __bfloat162float(h1));
    __nv_bfloat16 l2 = __float2bfloat16_rn(v.z - __bfloat162float(h2));
    __nv_bfloat16 l3 = __float2bfloat16_rn(v.w - __bfloat162float(h3));
    __nv_bfloat162* ph = (__nv_bfloat162*)(g_xhi + (size_t)i * 4);
    __nv_bfloat162* pl = (__nv_bfloat162*)(g_xlo + (size_t)i * 4);
    ph[0] = __nv_bfloat162(h0, h1); ph[1] = __nv_bfloat162(h2, h3);
    pl[0] = __nv_bfloat162(l0, l1); pl[1] = __nv_bfloat162(l2, l3);
}

// transpose + split weights: wt[which][n*256+k] = W_which[k*256+n]
__global__ void convert_w_kernel(const float* __restrict__ Wq, const float* __restrict__ Wk,
                                 const float* __restrict__ Wv, const float* __restrict__ Ws) {
    int i = blockIdx.x * blockDim.x + threadIdx.x;
    if (i >= 4 * HIDD * HIDD) return;
    int which = i >> 16;
    int r = i & 0xFFFF;
    int k = r >> 8, n = r & 255;
    const float* W = (which == 0) ? Wq : (which == 1) ? Wk : (which == 2) ? Wv : Ws;
    float v = W[k * HIDD + n];
    __nv_bfloat16 h = __float2bfloat16_rn(v);
    __nv_bfloat16 l = __float2bfloat16_rn(v - __bfloat162float(h));
    g_wthi[which * HIDD * HIDD + n * HIDD + k] = h;
    g_wtlo[which * HIDD * HIDD + n * HIDD + k] = l;
}

// ======================= HMMA GEMM (mma.sync bf16, 3-pass split, cp.async 2-buffer) =====
#define PITCH  80
#define AH_OFF 0
#define AL_OFF 10240
#define BH_OFF 20480
#define BL_OFF 30720
#define BUFSZ  40960

__global__ __launch_bounds__(256) void gemm_hmma_kernel(
    const float* __restrict__ bq, const float* __restrict__ bk,
    const float* __restrict__ bv, const float* __restrict__ bs, int M)
{
    extern __shared__ __align__(128) char smem[];
    uint32_t sb = smem_u32(smem);
    int tid = threadIdx.x, lane = tid & 31, wid = tid >> 5;
    int m0 = blockIdx.x * 128;
    int ntile = blockIdx.y;
    int which = blockIdx.z;
    int wm = wid & 3, wn = wid >> 2;

    const __nv_bfloat16* wtH = g_wthi + which * HIDD * HIDD;
    const __nv_bfloat16* wtL = g_wtlo + which * HIDD * HIDD;
    const float* bias = (which == 0) ? bq : (which == 1) ? bk : (which == 2) ? bv : bs;

    float acc[2][8][4];
#pragma unroll
    for (int mt = 0; mt < 2; mt++)
#pragma unroll
        for (int nt = 0; nt < 8; nt++)
#pragma unroll
            for (int j = 0; j < 4; j++) acc[mt][nt][j] = 0.f;

    auto stage = [&](int bb, int kc) {
        int k0 = kc * 32;
        uint32_t base = sb + (uint32_t)bb * BUFSZ;
#pragma unroll
        for (int it = 0; it < 2; it++) {
            int i = tid + it * 256;          // 0..511
            int r = i >> 2, c = i & 3;       // row 0..127, 16B chunk 0..3
            uint32_t so = (uint32_t)(r * PITCH + c * 16);
            int row = m0 + r;
            int ok = (row < M) ? 16 : 0;
            int srow = (row < M) ? row : 0;
            size_t asrc = (size_t)srow * HIDD + k0 + c * 8;
            cpa16(base + AH_OFF + so, g_xhi + asrc, ok);
            cpa16(base + AL_OFF + so, g_xlo + asrc, ok);
            size_t bsrc = (size_t)(ntile * 128 + r) * HIDD + k0 + c * 8;
            cpa16(base + BH_OFF + so, wtH + bsrc, 16);
            cpa16(base + BL_OFF + so, wtL + bsrc, 16);
        }
        CP_COMMIT();
    };

    stage(0, 0);
#pragma unroll 1
    for (int kc = 0; kc < 8; kc++) {
        int buf = kc & 1;
        if (kc < 7) { stage(buf ^ 1, kc + 1); CP_WAIT1(); }
        else        { CP_WAIT0(); }
        __syncthreads();

        uint32_t bbase = sb + (uint32_t)buf * BUFSZ;
#pragma unroll
        for (int s = 0; s < 2; s++) {
            uint32_t ah[2][4], al[2][4];
#pragma unroll
            for (int mt = 0; mt < 2; mt++) {
                uint32_t row = (uint32_t)(wm * 32 + mt * 16 + (lane & 15));
                uint32_t off = row * PITCH + (uint32_t)(s * 2 + (lane >> 4)) * 16;
                ldmat4(ah[mt], bbase + AH_OFF + off);
                ldmat4(al[mt], bbase + AL_OFF + off);
            }
#pragma unroll
            for (int ng = 0; ng < 4; ng++) {
                uint32_t nrow = (uint32_t)(wn * 64 + ng * 16 + (lane & 7) + ((lane >> 4) << 3));
                uint32_t off = nrow * PITCH + (uint32_t)(s * 2 + ((lane >> 3) & 1)) * 16;
                uint32_t bh[4], bl[4];
                ldmat4(bh, bbase + BH_OFF + off);
                ldmat4(bl, bbase + BL_OFF + off);
#pragma unroll
                for (int half = 0; half < 2; half++) {
                    int nt = ng * 2 + half;
#pragma unroll
                    for (int mt = 0; mt < 2; mt++) {
                        mma16816(acc[mt][nt], ah[mt], &bh[half * 2]);
                        mma16816(acc[mt][nt], al[mt], &bh[half * 2]);
                        mma16816(acc[mt][nt], ah[mt], &bl[half * 2]);
                    }
                }
            }
        }
        __syncthreads();
    }

    // ---- epilogue: +bias; q/skip -> fp32, k/v -> bf16 ----
    int colbase = ntile * 128 + wn * 64;
    int rbase = m0 + wm * 32 + (lane >> 2);
    bool is_bf16 = (which == 1) || (which == 2);
    float* Cf = (which == 0) ? g_q : g_skip;
    __nv_bfloat16* Cb = (which == 1) ? g_kb : g_vb;
#pragma unroll
    for (int mt = 0; mt < 2; mt++) {
#pragma unroll
        for (int nt = 0; nt < 8; nt++) {
            int col = colbase + nt * 8 + (lane & 3) * 2;
            float b0 = bias[col], b1 = bias[col + 1];
            int r0 = rbase + mt * 16;
            float v00 = acc[mt][nt][0] + b0, v01 = acc[mt][nt][1] + b1;
            float v10 = acc[mt][nt][2] + b0, v11 = acc[mt][nt][3] + b1;
            if (is_bf16) {
                if (r0 < M)
                    *(__nv_bfloat162*)(Cb + (size_t)r0 * HIDD + col) =
                        __nv_bfloat162(__float2bfloat16_rn(v00), __float2bfloat16_rn(v01));
                if (r0 + 8 < M)
                    *(__nv_bfloat162*)(Cb + (size_t)(r0 + 8) * HIDD + col) =
                        __nv_bfloat162(__float2bfloat16_rn(v10), __float2bfloat16_rn(v11));
            } else {
                if (r0 < M)
                    *(float2*)(Cf + (size_t)r0 * HIDD + col) = make_float2(v00, v01);
                if (r0 + 8 < M)
                    *(float2*)(Cf + (size_t)(r0 + 8) * HIDD + col) = make_float2(v10, v11);
            }
        }
    }
}

// ---------------- CSR build ----------------
__global__ void zero_counts_kernel(int n) {
    int i = blockIdx.x * blockDim.x + threadIdx.x;
    if (i < n) g_counts[i] = 0;
}

__global__ void hist_kernel(const int* __restrict__ ei, int E) {
    int e = blockIdx.x * blockDim.x + threadIdx.x;
    if (e < E) atomicAdd(&g_counts[ei[E + e]], 1);
}

// phase 1: per-block (1024-wide) local exclusive scan + block sums
__global__ __launch_bounds__(1024) void scan1_kernel(int n) {
    __shared__ int sh[1024];
    int t = threadIdx.x;
    int i = blockIdx.x * 1024 + t;
    int v = (i < n) ? g_counts[i] : 0;
    sh[t] = v;
    __syncthreads();
    for (int off = 1; off < 1024; off <<= 1) {
        int add = (t >= off) ? sh[t - off] : 0;
        __syncthreads();
        sh[t] += add;
        __syncthreads();
    }
    if (i < n) g_off[i] = sh[t] - v;         // block-local exclusive
    if (t == 1023) g_bsum[blockIdx.x] = sh[1023];
}

// phase 2: scan the (<=64) block sums; also writes g_off[n] = total
__global__ void scan2_kernel(int nb, int n) {
    __shared__ int sh[64];
    int t = threadIdx.x;                     // 64 threads
    int v = (t < nb) ? g_bsum[t] : 0;
    sh[t] = v;
    __syncthreads();
    for (int off = 1; off < 64; off <<= 1) {
        int add = (t >= off) ? sh[t - off] : 0;
        __syncthreads();
        sh[t] += add;
        __syncthreads();
    }
    if (t < nb) g_bsum[t] = sh[t] - v;       // exclusive block offsets
    if (t == 63) g_off[n] = sh[63];
}

// phase 3: add block offsets, init cursor
__global__ __launch_bounds__(1024) void scan3_kernel(int n) {
    int i = blockIdx.x * 1024 + threadIdx.x;
    if (i < n) {
        int o = g_off[i] + g_bsum[i >> 10];
        g_off[i] = o;
        g_cur[i] = o;
    }
}

__global__ void scatter_kernel(const int* __restrict__ ei, int E) {
    int e = blockIdx.x * blockDim.x + threadIdx.x;
    if (e < E) {
        int d = ei[E + e];
        int p = atomicAdd(&g_cur[d], 1);
        g_perm[p] = e;
    }
}

// sort each CSR segment by edge id -> deterministic order regardless of the
// nondeterministic atomic scatter. One thread per node; insertion sort (deg~16).
__global__ void sort_kernel(int n) {
    int i = blockIdx.x * blockDim.x + threadIdx.x;
    if (i >= n) return;
    int beg = g_off[i], end = g_off[i + 1];
    for (int a = beg + 1; a < end; a++) {
        int v = g_perm[a];
        int b = a - 1;
        while (b >= beg && g_perm[b] > v) { g_perm[b + 1] = g_perm[b]; b--; }
        g_perm[b + 1] = v;
    }
}

// resolve edge ids to source node ids (drops one indirection from attn loop)
__global__ void resolve_kernel(const int* __restrict__ ei, int E) {
    int p = blockIdx.x * blockDim.x + threadIdx.x;
    if (p < E) g_src[p] = ei[g_perm[p]];
}

// ---------------- attention + epilogue: one warp per dst node ----------------
// g_src pre-sorted & resolved -> sequential walk, deterministic. k/v in bf16.
__global__ __launch_bounds__(256) void attn_kernel(
    const float* __restrict__ x,
    const float* __restrict__ gamma, const float* __restrict__ beta,
    float* __restrict__ out, int n)
{
    int gw = (blockIdx.x * blockDim.x + threadIdx.x) >> 5;
    if (gw >= n) return;
    int lane = threadIdx.x & 31;
    int col0 = ((lane >> 2) << 5) + ((lane & 3) << 3);   // h*32 + sub*8
    size_t rowbase = (size_t)gw * HIDD;

    float qf[8];
    {
        float4 q0 = *(const float4*)(g_q + rowbase + col0);
        float4 q1 = *(const float4*)(g_q + rowbase + col0 + 4);
        qf[0] = q0.x; qf[1] = q0.y; qf[2] = q0.z; qf[3] = q0.w;
        qf[4] = q1.x; qf[5] = q1.y; qf[6] = q1.z; qf[7] = q1.w;
    }

    float m = -FLT_MAX, l = 0.f;
    float acc[8];
#pragma unroll
    for (int j = 0; j < 8; j++) acc[j] = 0.f;

    int beg = g_off[gw], end = g_off[gw + 1];
    const float rsD = 0.17677669529663689f;   // 1/sqrt(32)

    int src_next = (beg < end) ? g_src[beg] : 0;
#pragma unroll 1
    for (int p_ = beg; p_ < end; p_++) {
        int src = src_next;
        if (p_ + 1 < end) src_next = g_src[p_ + 1];

        size_t sbase = (size_t)src * HIDD + col0;
        uint4 kr = *(const uint4*)(g_kb + sbase);   // 8 bf16 = 16 B
        uint4 vr = *(const uint4*)(g_vb + sbase);

        float2 k0 = __bfloat1622float2(*(__nv_bfloat162*)&kr.x);
        float2 k1 = __bfloat1622float2(*(__nv_bfloat162*)&kr.y);
        float2 k2 = __bfloat1622float2(*(__nv_bfloat162*)&kr.z);
        float2 k3 = __bfloat1622float2(*(__nv_bfloat162*)&kr.w);
        float d = qf[0] * k0.x + qf[1] * k0.y + qf[2] * k1.x + qf[3] * k1.y
                + qf[4] * k2.x + qf[5] * k2.y + qf[6] * k3.x + qf[7] * k3.y;
        d += __shfl_xor_sync(0xffffffffu, d, 1);
        d += __shfl_xor_sync(0xffffffffu, d, 2);
        float logit = d * rsD;

        float mnew = fmaxf(m, logit);
        float sc   = __expf(m - mnew);       // first edge: exp(-inf) = 0
        float p    = __expf(logit - mnew);
        m = mnew;
        l = l * sc + p;

        float2 v0 = __bfloat1622float2(*(__nv_bfloat162*)&vr.x);
        float2 v1 = __bfloat1622float2(*(__nv_bfloat162*)&vr.y);
        float2 v2 = __bfloat1622float2(*(__nv_bfloat162*)&vr.z);
        float2 v3 = __bfloat1622float2(*(__nv_bfloat162*)&vr.w);
        acc[0] = acc[0] * sc + p * v0.x;
        acc[1] = acc[1] * sc + p * v0.y;
        acc[2] = acc[2] * sc + p * v1.x;
        acc[3] = acc[3] * sc + p * v1.y;
        acc[4] = acc[4] * sc + p * v2.x;
        acc[5] = acc[5] * sc + p * v2.y;
        acc[6] = acc[6] * sc + p * v3.x;
        acc[7] = acc[7] * sc + p * v3.y;
    }

    float inv = (l > 0.f) ? (1.f / l) : 0.f;

    const float* xr = x      + rowbase + col0;
    const float* sk = g_skip + rowbase + col0;
    float y[8];
    float s1 = 0.f, s2 = 0.f;
#pragma unroll
    for (int j = 0; j < 8; j++) {
        float o  = acc[j] * inv + sk[j];
        float g  = 0.5f * o * (1.f + erff(o * 0.70710678118654752f));
        float yy = xr[j] + g;
        y[j] = yy;
        s1 += yy;
        s2 += yy * yy;
    }
#pragma unroll
    for (int o = 16; o; o >>= 1) {
        s1 += __shfl_xor_sync(0xffffffffu, s1, o);
        s2 += __shfl_xor_sync(0xffffffffu, s2, o);
    }
    float mean = s1 * (1.f / 256.f);
    float var  = s2 * (1.f / 256.f) - mean * mean;
    float istd = rsqrtf(var + 1e-5f);
#pragma unroll
    for (int j = 0; j < 8; j++)
        out[rowbase + col0 + j] = (y[j] - mean) * istd * gamma[col0 + j] + beta[col0 + j];
}

// ---------------- launch ----------------
extern "C" void kernel_launch(void* const* d_in, const int* in_sizes, int n_in,
                              void* d_out, int out_size)
{
    const float* x     = (const float*)d_in[0];
    const int*   ei    = (const int*)d_in[1];      // int32 (2, E) row-major
    const float* Wq    = (const float*)d_in[2];
    const float* bq    = (const float*)d_in[3];
    const float* Wk    = (const float*)d_in[4];
    const float* bk    = (const float*)d_in[5];
    const float* Wv    = (const float*)d_in[6];
    const float* bv    = (const float*)d_in[7];
    const float* Wsk   = (const float*)d_in[8];
    const float* bsk   = (const float*)d_in[9];
    const float* gamma = (const float*)d_in[10];
    const float* beta  = (const float*)d_in[11];
    float* out = (float*)d_out;

    int n = in_sizes[0] / HIDD;     // 50000
    int E = in_sizes[1] / 2;        // 800000

    cudaFuncSetAttribute(gemm_hmma_kernel,
                         cudaFuncAttributeMaxDynamicSharedMemorySize, 2 * BUFSZ);

    int total4 = n * HIDD / 4;
    int nb = (n + 1023) / 1024;     // 49 scan blocks

    // launch order puts gemm at idx 3 (the slot ncu's -s/-c window has captured
    // in prior rounds) for telemetry.
    convert_x_kernel<<<(total4 + 255) / 256, 256>>>(x, total4);
    convert_w_kernel<<<(4 * HIDD * HIDD + 255) / 256, 256>>>(Wq, Wk, Wv, Wsk);
    zero_counts_kernel<<<(n + 255) / 256, 256>>>(n);

    dim3 ggrid((n + 127) / 128, 2, 4);
    gemm_hmma_kernel<<<ggrid, 256, 2 * BUFSZ>>>(bq, bk, bv, bsk, n);

    hist_kernel<<<(E + 255) / 256, 256>>>(ei, E);
    scan1_kernel<<<nb, 1024>>>(n);
    scan2_kernel<<<1, 64>>>(nb, n);
    scan3_kernel<<<nb, 1024>>>(n);
    scatter_kernel<<<(E + 255) / 256, 256>>>(ei, E);
    sort_kernel<<<(n + 255) / 256, 256>>>(n);
    resolve_kernel<<<(E + 255) / 256, 256>>>(ei, E);

    attn_kernel<<<(n * 32 + 255) / 256, 256>>>(x, gamma, beta, out, n);
}